// round 3
// baseline (speedup 1.0000x reference)
#include <cuda_runtime.h>
#include <cuda_bf16.h>
#include <cstdint>

// ---------------------------------------------------------------------------
// Persistent 2-layer tanh RNN.  B=64, T=512, D=H0=H1=1024, K=2048.
// 128 CTAs: blockIdx 0..63 = layer0 (cols 16*cta), 64..127 = layer1.
// Layer-pipelined phases p=0..512:
//   layer0 at phase p computes h0[t=p]      (reads h0[p-1], x[p])
//   layer1 at phase p computes h1[t=p-1]    (reads h1[p-2], h0[p-1])
// Grid barrier (epoch-based, monotonic counter) between phases.
// Weights in SMEM fp32; A=[h;inp] staged in SMEM via double-buffered
// cp.async.cg (L2-only => coherent with st.global.cg hidden-state writes).
// Math: packed fp32x2 FMA (fma.rn.f32x2) over column pairs.
// ---------------------------------------------------------------------------

#define BZ      64
#define TT      512
#define DD      1024
#define HH      1024
#define KDIM    2048
#define NCOL    16
#define THREADS 128
#define NCTA    128
#define CHUNK   128
#define NCHUNK  (KDIM / CHUNK)      // 16
#define KP4     33                  // float4 stride per batch row in A smem (pad)
#define A_F4    (BZ * KP4)          // 2112 float4 per A buffer
#define W_F4    (KDIM * 4)          // 8192 float4 for 2048x16 weights
#define SMEM_BYTES ((W_F4 + 2 * A_F4) * 16)   // 198656 B

// Persistent scratch (no allocations allowed)
__device__ float g_h0[2][BZ * HH];
__device__ float g_h1[2][BZ * HH];
__device__ int          g_count;
__device__ volatile int g_epoch;

// ---------------------------------------------------------------------------
__global__ void prep_kernel() {
    int i = blockIdx.x * blockDim.x + threadIdx.x;
    int stride = gridDim.x * blockDim.x;
    float* a = &g_h0[0][0];
    float* b = &g_h1[0][0];
    for (int k = i; k < 2 * BZ * HH; k += stride) { a[k] = 0.f; b[k] = 0.f; }
    if (i == 0) { g_count = 0; g_epoch = 0; }
}

// ---------------------------------------------------------------------------
__device__ __forceinline__ unsigned long long pack2(float x, float y) {
    unsigned long long r;
    asm("mov.b64 %0, {%1, %2};" : "=l"(r) : "f"(x), "f"(y));
    return r;
}
__device__ __forceinline__ float2 unpack2(unsigned long long v) {
    float2 r;
    asm("mov.b64 {%0, %1}, %2;" : "=f"(r.x), "=f"(r.y) : "l"(v));
    return r;
}
__device__ __forceinline__ void fma2(unsigned long long& d,
                                     unsigned long long a,
                                     unsigned long long b) {
    asm("fma.rn.f32x2 %0, %1, %2, %0;" : "+l"(d) : "l"(a), "l"(b));
}
__device__ __forceinline__ void cp16(uint32_t dst_smem, const void* src) {
    asm volatile("cp.async.cg.shared.global [%0], [%1], 16;" :: "r"(dst_smem), "l"(src));
}
__device__ __forceinline__ void cp_commit() {
    asm volatile("cp.async.commit_group;");
}
template <int N>
__device__ __forceinline__ void cp_wait() {
    asm volatile("cp.async.wait_group %0;" :: "n"(N));
}

// Copy one 64b x 128k chunk (2048 float4) global -> A smem buffer.
__device__ __forceinline__ void load_chunk(float4* dst, const float* sp,
                                           long bstride, int koff, int tid) {
#pragma unroll
    for (int i = 0; i < 16; i++) {
        int idx = i * 128 + tid;          // 0..2047
        int b   = idx >> 5;
        int kq  = idx & 31;
        const float* g = sp + (long)b * bstride + koff + kq * 4;
        uint32_t d = (uint32_t)__cvta_generic_to_shared(dst + b * KP4 + kq);
        cp16(d, g);
    }
    cp_commit();
}

// ---------------------------------------------------------------------------
__global__ void __launch_bounds__(THREADS, 1)
rnn_persistent_kernel(const float* __restrict__ x,
                      const float* __restrict__ W0,
                      const float* __restrict__ b0,
                      const float* __restrict__ W1,
                      const float* __restrict__ b1,
                      float* __restrict__ out) {
    extern __shared__ float4 smem4[];
    float4* Ws4 = smem4;                 // [2048][4] float4  (W[k][16 cols])
    float4* As4 = smem4 + W_F4;          // 2 buffers of A_F4

    const int tid   = threadIdx.x;
    const int cta   = blockIdx.x;
    const int layer = cta >> 6;
    const int jcta  = (cta & 63) * NCOL;

    const float* W    = layer ? W1 : W0;
    const float* bias = layer ? b1 : b0;

    // One-time: weights into SMEM (k-major, 16 cols per CTA)
    for (int n = tid; n < W_F4; n += THREADS) {
        int k = n >> 2, q = n & 3;
        Ws4[n] = *reinterpret_cast<const float4*>(W + (long)k * 1024 + jcta + q * 4);
    }

    const int bg  = tid & 31;            // batch group: b0i=bg, b1i=bg+32
    const int jg  = tid >> 5;            // 0..3 -> cols jcta + 4*jg ..
    const int b0i = bg, b1i = bg + 32;
    const int jcol = jcta + jg * 4;

    const float4 bv = *reinterpret_cast<const float4*>(bias + jcol);
    const unsigned long long* W2 = reinterpret_cast<const unsigned long long*>(Ws4);
    const size_t FSOFF = (size_t)BZ * TT * HH;

    __syncthreads();

    for (int p = 0; p <= TT; p++) {
        const bool active = layer ? (p >= 1) : (p < TT);
        if (active) {
            const int t = layer ? (p - 1) : p;
            // half0 source: own-layer previous hidden
            const float* sp0 = layer ? g_h1[p & 1] : g_h0[(p + 1) & 1];
            // half1 source: x[t] (layer0) or h0[t] (layer1)
            const float* sp1 = layer ? g_h0[(p + 1) & 1] : (x + (long)t * DD);
            const long   bs1 = layer ? (long)HH : (long)TT * DD;

            unsigned long long c00 = 0ull, c01 = 0ull, c10 = 0ull, c11 = 0ull;

            // prime chunk 0
            load_chunk(As4, sp0, HH, 0, tid);

            for (int c = 0; c < NCHUNK; c++) {
                // prefetch next chunk into other buffer
                if (c + 1 < NCHUNK) {
                    int k0n = (c + 1) * CHUNK;
                    if (k0n < 1024)
                        load_chunk(As4 + ((c + 1) & 1) * A_F4, sp0, HH, k0n, tid);
                    else
                        load_chunk(As4 + ((c + 1) & 1) * A_F4, sp1, bs1, k0n - 1024, tid);
                    cp_wait<1>();
                } else {
                    cp_wait<0>();
                }
                __syncthreads();

                const float4* Ab = As4 + (c & 1) * A_F4;
                const int kbase = c * CHUNK;
#pragma unroll 4
                for (int kq = 0; kq < 32; kq++) {
                    float4 a0 = Ab[b0i * KP4 + kq];
                    float4 a1 = Ab[b1i * KP4 + kq];
                    int k = kbase + kq * 4;
#pragma unroll
                    for (int u = 0; u < 4; u++) {
                        unsigned long long wlo = W2[((long)(k + u) * 4 + jg) * 2 + 0];
                        unsigned long long whi = W2[((long)(k + u) * 4 + jg) * 2 + 1];
                        float av0 = (&a0.x)[u];
                        float av1 = (&a1.x)[u];
                        unsigned long long d0 = pack2(av0, av0);
                        unsigned long long d1 = pack2(av1, av1);
                        fma2(c00, d0, wlo);
                        fma2(c01, d0, whi);
                        fma2(c10, d1, wlo);
                        fma2(c11, d1, whi);
                    }
                }
                __syncthreads();
            }

            // epilogue: bias + tanh + stores
            float2 r00 = unpack2(c00), r01 = unpack2(c01);
            float2 r10 = unpack2(c10), r11 = unpack2(c11);
            float4 o0, o1;
            o0.x = tanhf(r00.x + bv.x); o0.y = tanhf(r00.y + bv.y);
            o0.z = tanhf(r01.x + bv.z); o0.w = tanhf(r01.y + bv.w);
            o1.x = tanhf(r10.x + bv.x); o1.y = tanhf(r10.y + bv.y);
            o1.z = tanhf(r11.x + bv.z); o1.w = tanhf(r11.y + bv.w);

            if (layer == 0) {
                float* hw = g_h0[p & 1];
                __stcg(reinterpret_cast<float4*>(hw + b0i * HH + jcol), o0);
                __stcg(reinterpret_cast<float4*>(hw + b1i * HH + jcol), o1);
                if (p == TT - 1) {
                    *reinterpret_cast<float4*>(out + FSOFF + (size_t)b0i * 2048 + jcol) = o0;
                    *reinterpret_cast<float4*>(out + FSOFF + (size_t)b1i * 2048 + jcol) = o1;
                }
            } else {
                float* hw = g_h1[(p + 1) & 1];
                __stcg(reinterpret_cast<float4*>(hw + b0i * HH + jcol), o0);
                __stcg(reinterpret_cast<float4*>(hw + b1i * HH + jcol), o1);
                *reinterpret_cast<float4*>(out + (size_t)b0i * TT * HH + (size_t)t * HH + jcol) = o0;
                *reinterpret_cast<float4*>(out + (size_t)b1i * TT * HH + (size_t)t * HH + jcol) = o1;
                if (t == TT - 1) {
                    *reinterpret_cast<float4*>(out + FSOFF + (size_t)b0i * 2048 + 1024 + jcol) = o0;
                    *reinterpret_cast<float4*>(out + FSOFF + (size_t)b1i * 2048 + 1024 + jcol) = o1;
                }
            }
        }

        // ---- grid barrier (epoch-based) ----
        __threadfence();
        __syncthreads();
        if (tid == 0) {
            int e = g_epoch;
            int old = atomicAdd(&g_count, 1);
            if (((old + 1) & (NCTA - 1)) == 0) {
                __threadfence();
                atomicAdd((int*)&g_epoch, 1);
            } else {
                while (g_epoch == e) { __nanosleep(64); }
            }
        }
        __syncthreads();
    }
}

// ---------------------------------------------------------------------------
extern "C" void kernel_launch(void* const* d_in, const int* in_sizes, int n_in,
                              void* d_out, int out_size) {
    const float* x  = (const float*)d_in[0];
    const float* W0 = (const float*)d_in[1];
    const float* b0 = (const float*)d_in[2];
    const float* W1 = (const float*)d_in[3];
    const float* b1 = (const float*)d_in[4];
    float* out = (float*)d_out;

    cudaFuncSetAttribute(rnn_persistent_kernel,
                         cudaFuncAttributeMaxDynamicSharedMemorySize, SMEM_BYTES);

    prep_kernel<<<64, 256>>>();
    rnn_persistent_kernel<<<NCTA, THREADS, SMEM_BYTES>>>(x, W0, b0, W1, b1, out);
}

// round 5
// speedup vs baseline: 2.9826x; 2.9826x over previous
#include <cuda_runtime.h>
#include <cuda_bf16.h>
#include <cstdint>

#define TT 512
#define HH 1024
#define KDIM 2048
#define NCOL 16
#define THREADS 256
#define NCTA 128

// smem byte offsets
#define W_STRIDE 4112            // 2048 bf16 + 16B pad per n-row
#define WH_OFF 0                 // 16 * 4112 = 65792
#define WL_OFF 65792
#define A_OFF  131584
#define A_STRIDE 272             // 128 bf16 chunk + 16B pad per A row
#define A_BUF  34816             // 128 rows * 272
#define STAGE_OFF 201216         // 128 * 20 * 4 = 10240
#define SMEM_BYTES 211456

__device__ __nv_bfloat16 g_xs[(size_t)128 * TT * 1024];   // x split planes: b<64 hi, b+64 lo
__device__ __nv_bfloat16 g_h0s[2][128 * 1024];
__device__ __nv_bfloat16 g_h1s[2][128 * 1024];
__device__ int g_count;
__device__ volatile int g_epoch;

// ---------------------------------------------------------------------------
__device__ __forceinline__ uint32_t smem_u32(const void* p) {
    uint32_t a;
    asm("{ .reg .u64 t; cvta.to.shared.u64 t, %1; cvt.u32.u64 %0, t; }" : "=r"(a) : "l"(p));
    return a;
}
__device__ __forceinline__ void cp16(uint32_t d, const void* s) {
    asm volatile("cp.async.cg.shared.global [%0], [%1], 16;" :: "r"(d), "l"(s));
}
__device__ __forceinline__ void cp_commit() { asm volatile("cp.async.commit_group;"); }
template <int N>
__device__ __forceinline__ void cp_wait() { asm volatile("cp.async.wait_group %0;" :: "n"(N)); }

__device__ __forceinline__ void ldsm4(uint32_t* r, uint32_t addr) {
    asm volatile("ldmatrix.sync.aligned.m8n8.x4.shared.b16 {%0,%1,%2,%3}, [%4];"
        : "=r"(r[0]), "=r"(r[1]), "=r"(r[2]), "=r"(r[3]) : "r"(addr));
}
__device__ __forceinline__ void mma16816(float* c, const uint32_t* a, uint32_t b0, uint32_t b1) {
    asm volatile("mma.sync.aligned.m16n8k16.row.col.f32.bf16.bf16.f32 "
        "{%0,%1,%2,%3}, {%4,%5,%6,%7}, {%8,%9}, {%0,%1,%2,%3};"
        : "+f"(c[0]), "+f"(c[1]), "+f"(c[2]), "+f"(c[3])
        : "r"(a[0]), "r"(a[1]), "r"(a[2]), "r"(a[3]), "r"(b0), "r"(b1));
}

// ---------------------------------------------------------------------------
__global__ void prep_state() {
    int i = blockIdx.x * blockDim.x + threadIdx.x, st = gridDim.x * blockDim.x;
    __nv_bfloat16 z = __float2bfloat16(0.f);
    for (int k = i; k < 2 * 128 * 1024; k += st) { g_h0s[0][k] = z; g_h1s[0][k] = z; }
    if (i == 0) { g_count = 0; g_epoch = 0; }
}
__global__ void prep_split_x(const float* __restrict__ x) {
    size_t i = (size_t)blockIdx.x * blockDim.x + threadIdx.x;
    size_t st = (size_t)gridDim.x * blockDim.x;
    const size_t N = (size_t)64 * TT * 1024;
    for (size_t k = i; k < N; k += st) {
        float v = x[k];
        __nv_bfloat16 hi = __float2bfloat16(v);
        __nv_bfloat16 lo = __float2bfloat16(v - __bfloat162float(hi));
        size_t b = k >> 19, rest = k & ((1u << 19) - 1);   // T*H = 2^19
        g_xs[b * (size_t)(TT * 1024) + rest] = hi;
        g_xs[(b + 64) * (size_t)(TT * 1024) + rest] = lo;
    }
}

// ---------------------------------------------------------------------------
__global__ void __launch_bounds__(THREADS, 1)
rnn_mma_kernel(const float* __restrict__ W0, const float* __restrict__ b0,
               const float* __restrict__ W1, const float* __restrict__ b1,
               float* __restrict__ out) {
    extern __shared__ char smem[];
    const uint32_t sb = smem_u32(smem);
    float* stage = (float*)(smem + STAGE_OFF);
    const int tid = threadIdx.x, w = tid >> 5, lane = tid & 31;
    const int cta = blockIdx.x, layer = cta >> 6, jcta = (cta & 63) * NCOL;
    const float* Wg   = layer ? W1 : W0;
    const float* bias = layer ? b1 : b0;

    // one-time: split W into SMEM, layout [n][k] bf16, row stride 4112B
    for (int i = tid; i < KDIM * NCOL; i += THREADS) {
        int k = i >> 4, n = i & 15;
        float v = Wg[(size_t)k * 1024 + jcta + n];
        __nv_bfloat16 hi = __float2bfloat16(v);
        __nv_bfloat16 lo = __float2bfloat16(v - __bfloat162float(hi));
        *(__nv_bfloat16*)(smem + WH_OFF + n * W_STRIDE + k * 2) = hi;
        *(__nv_bfloat16*)(smem + WL_OFF + n * W_STRIDE + k * 2) = lo;
    }

    // per-thread epilogue constants
    const int eb = tid >> 2, en0 = (tid & 3) * 4;
    float bv[4];
#pragma unroll
    for (int q = 0; q < 4; q++) bv[q] = bias[jcta + en0 + q];

    // mma-warp ldmatrix address bases
    const uint32_t a_base = sb + A_OFF + (uint32_t)(32 * (w & 3) + (lane & 15)) * A_STRIDE
                          + (uint32_t)(lane >> 4) * 16;
    const int bn = (lane & 7) + ((lane >> 4) << 3);
    const uint32_t bh_base = sb + WH_OFF + (uint32_t)bn * W_STRIDE + (uint32_t)((lane >> 3) & 1) * 16;
    const uint32_t bl_base = bh_base + (WL_OFF - WH_OFF);

    const size_t FSOFF = (size_t)64 * TT * HH;
    __syncthreads();

    for (int p = 0; p <= TT; p++) {
        const bool active = layer ? (p >= 1) : (p < TT);
        if (active) {
            const int t = layer ? (p - 1) : p;
            const __nv_bfloat16* s0;
            const __nv_bfloat16* s1;
            size_t rst1;
            if (layer) { s0 = g_h1s[(p + 1) & 1]; s1 = g_h0s[(p + 1) & 1]; rst1 = 1024; }
            else       { s0 = g_h0s[(p + 1) & 1]; s1 = g_xs + (size_t)t * 1024; rst1 = (size_t)TT * 1024; }

            float acc[2][2][2][4];
#pragma unroll
            for (int i = 0; i < 32; i++) (&acc[0][0][0][0])[i] = 0.f;

            // prologue: loaders stage chunk 0
            if (w >= 4) {
                const int tid2 = tid & 127, seg = tid2 & 15, rb = tid2 >> 4;
                const uint32_t db0 = sb + A_OFF + (uint32_t)rb * A_STRIDE + seg * 16;
                // chunk 0 is always from s0 (k<1024)
                const __nv_bfloat16* sp = s0 + (size_t)rb * 1024 + seg * 8;
#pragma unroll
                for (int j = 0; j < 16; j++)
                    cp16(db0 + j * 8 * A_STRIDE, sp + (size_t)8 * j * 1024);
                cp_commit();
            }

            for (int c = 0; c < 16; c++) {
                if (w >= 4) {
                    if (c + 1 < 16) {
                        const int kb = (c + 1) * 128;
                        const __nv_bfloat16* srcb;
                        size_t rst;
                        if (kb < 1024) { srcb = s0 + kb; rst = 1024; }
                        else           { srcb = s1 + (kb - 1024); rst = rst1; }
                        const int tid2 = tid & 127, seg = tid2 & 15, rb = tid2 >> 4;
                        const uint32_t db = sb + A_OFF + (uint32_t)((c + 1) & 1) * A_BUF
                                          + (uint32_t)rb * A_STRIDE + seg * 16;
                        const __nv_bfloat16* sp = srcb + (size_t)rb * rst + seg * 8;
#pragma unroll
                        for (int j = 0; j < 16; j++)
                            cp16(db + j * 8 * A_STRIDE, sp + (size_t)8 * j * rst);
                        cp_commit();
                        cp_wait<1>();
                    } else {
                        cp_wait<0>();
                    }
                }
                __syncthreads();

                if (w < 4) {
                    const uint32_t ab = a_base + (uint32_t)(c & 1) * A_BUF;
                    const uint32_t bo = (uint32_t)c * 256;
#pragma unroll
                    for (int s = 0; s < 8; s++) {
                        uint32_t A0[4], A1[4], BH[4], BL[4];
                        ldsm4(A0, ab + s * 32);
                        ldsm4(A1, ab + 16 * A_STRIDE + s * 32);
                        ldsm4(BH, bh_base + bo + s * 32);
                        ldsm4(BL, bl_base + bo + s * 32);
                        mma16816(acc[0][0][0], A0, BH[0], BH[1]);
                        mma16816(acc[0][1][0], A0, BH[2], BH[3]);
                        mma16816(acc[1][0][0], A1, BH[0], BH[1]);
                        mma16816(acc[1][1][0], A1, BH[2], BH[3]);
                        mma16816(acc[0][0][1], A0, BL[0], BL[1]);
                        mma16816(acc[0][1][1], A0, BL[2], BL[3]);
                        mma16816(acc[1][0][1], A1, BL[0], BL[1]);
                        mma16816(acc[1][1][1], A1, BL[2], BL[3]);
                    }
                }
                __syncthreads();
            }

            // write C fragments (hi+lo W splits pre-summed) to stage
            if (w < 4) {
                const int r0 = 32 * w + (lane >> 2);
                const int cc = 2 * (lane & 3);
#pragma unroll
                for (int mt = 0; mt < 2; mt++)
#pragma unroll
                    for (int nt = 0; nt < 2; nt++) {
                        const float* c0 = acc[mt][nt][0];
                        const float* c1 = acc[mt][nt][1];
                        const int col = 8 * nt + cc;
                        stage[(r0 + 16 * mt) * 20 + col]         = c0[0] + c1[0];
                        stage[(r0 + 16 * mt) * 20 + col + 1]     = c0[1] + c1[1];
                        stage[(r0 + 16 * mt + 8) * 20 + col]     = c0[2] + c1[2];
                        stage[(r0 + 16 * mt + 8) * 20 + col + 1] = c0[3] + c1[3];
                    }
            }
            __syncthreads();

            // combine hi/lo A rows, bias, tanh, split-store h, write outputs
            {
                float4 vh = *(float4*)&stage[eb * 20 + en0];
                float4 vl = *(float4*)&stage[(eb + 64) * 20 + en0];
                float h[4];
                h[0] = tanhf(vh.x + vl.x + bv[0]);
                h[1] = tanhf(vh.y + vl.y + bv[1]);
                h[2] = tanhf(vh.z + vl.z + bv[2]);
                h[3] = tanhf(vh.w + vl.w + bv[3]);

                uint32_t hw[2], lw[2];
#pragma unroll
                for (int q = 0; q < 2; q++) {
                    __nv_bfloat16 h0 = __float2bfloat16(h[2 * q]);
                    __nv_bfloat16 h1 = __float2bfloat16(h[2 * q + 1]);
                    __nv_bfloat16 l0 = __float2bfloat16(h[2 * q] - __bfloat162float(h0));
                    __nv_bfloat16 l1 = __float2bfloat16(h[2 * q + 1] - __bfloat162float(h1));
                    hw[q] = (uint32_t)*(uint16_t*)&h0 | ((uint32_t)*(uint16_t*)&h1 << 16);
                    lw[q] = (uint32_t)*(uint16_t*)&l0 | ((uint32_t)*(uint16_t*)&l1 << 16);
                }
                __nv_bfloat16* hp = layer ? g_h1s[p & 1] : g_h0s[p & 1];
                __stcg((uint2*)(hp + (size_t)eb * 1024 + jcta + en0), make_uint2(hw[0], hw[1]));
                __stcg((uint2*)(hp + (size_t)(eb + 64) * 1024 + jcta + en0), make_uint2(lw[0], lw[1]));

                float4 of = make_float4(h[0], h[1], h[2], h[3]);
                if (layer) {
                    *(float4*)(out + ((size_t)eb * TT + t) * HH + jcta + en0) = of;
                    if (t == TT - 1)
                        *(float4*)(out + FSOFF + (size_t)eb * 2048 + 1024 + jcta + en0) = of;
                } else if (p == TT - 1) {
                    *(float4*)(out + FSOFF + (size_t)eb * 2048 + jcta + en0) = of;
                }
            }
        }

        // ---- grid barrier (epoch-based) ----
        __threadfence();
        __syncthreads();
        if (tid == 0) {
            int e = g_epoch;
            int old = atomicAdd(&g_count, 1);
            if (((old + 1) & (NCTA - 1)) == 0) {
                __threadfence();
                atomicAdd((int*)&g_epoch, 1);
            } else {
                while (g_epoch == e) { __nanosleep(64); }
            }
        }
        __syncthreads();
    }
}

// ---------------------------------------------------------------------------
extern "C" void kernel_launch(void* const* d_in, const int* in_sizes, int n_in,
                              void* d_out, int out_size) {
    const float* x  = (const float*)d_in[0];
    const float* W0 = (const float*)d_in[1];
    const float* b0 = (const float*)d_in[2];
    const float* W1 = (const float*)d_in[3];
    const float* b1 = (const float*)d_in[4];
    float* out = (float*)d_out;

    cudaFuncSetAttribute(rnn_mma_kernel,
                         cudaFuncAttributeMaxDynamicSharedMemorySize, SMEM_BYTES);
    prep_state<<<64, 256>>>();
    prep_split_x<<<256, 256>>>(x);
    rnn_mma_kernel<<<NCTA, THREADS, SMEM_BYTES>>>(W0, b0, W1, b1, out);
}

// round 6
// speedup vs baseline: 3.0535x; 1.0238x over previous
#include <cuda_runtime.h>
#include <cuda_bf16.h>
#include <cstdint>

#define TT 512
#define HH 1024
#define KDIM 2048
#define NCOL 16
#define THREADS 256
#define NCTA 128

// smem byte offsets
#define W_STRIDE 4112            // 2048 bf16 + 16B pad per n-row
#define WH_OFF 0                 // 16 * 4112 = 65792
#define WL_OFF 65792
#define A_OFF  131584
#define A_STRIDE 272             // 128 bf16 chunk + 16B pad per A row
#define A_BUF  34816             // 128 rows * 272
#define STAGE_OFF 201216         // 2 * 128 * 20 * 4 = 20480
#define SMEM_BYTES 221696

__device__ __nv_bfloat16 g_xs[(size_t)128 * TT * 1024];   // x split planes: b<64 hi, b+64 lo
__device__ __nv_bfloat16 g_h0s[2][128 * 1024];
__device__ __nv_bfloat16 g_h1s[2][128 * 1024];
__device__ int g_cnt[TT + 2];

// ---------------------------------------------------------------------------
__device__ __forceinline__ uint32_t smem_u32(const void* p) {
    uint32_t a;
    asm("{ .reg .u64 t; cvta.to.shared.u64 t, %1; cvt.u32.u64 %0, t; }" : "=r"(a) : "l"(p));
    return a;
}
__device__ __forceinline__ void cp16(uint32_t d, const void* s) {
    asm volatile("cp.async.cg.shared.global [%0], [%1], 16;" :: "r"(d), "l"(s));
}
__device__ __forceinline__ void cp_commit() { asm volatile("cp.async.commit_group;"); }
template <int N>
__device__ __forceinline__ void cp_wait() { asm volatile("cp.async.wait_group %0;" :: "n"(N)); }

__device__ __forceinline__ void ldsm4(uint32_t* r, uint32_t addr) {
    asm volatile("ldmatrix.sync.aligned.m8n8.x4.shared.b16 {%0,%1,%2,%3}, [%4];"
        : "=r"(r[0]), "=r"(r[1]), "=r"(r[2]), "=r"(r[3]) : "r"(addr));
}
__device__ __forceinline__ void mma16816(float* c, const uint32_t* a, uint32_t b0, uint32_t b1) {
    asm volatile("mma.sync.aligned.m16n8k16.row.col.f32.bf16.bf16.f32 "
        "{%0,%1,%2,%3}, {%4,%5,%6,%7}, {%8,%9}, {%0,%1,%2,%3};"
        : "+f"(c[0]), "+f"(c[1]), "+f"(c[2]), "+f"(c[3])
        : "r"(a[0]), "r"(a[1]), "r"(a[2]), "r"(a[3]), "r"(b0), "r"(b1));
}

// ---------------------------------------------------------------------------
__global__ void prep_state() {
    int i = blockIdx.x * blockDim.x + threadIdx.x, st = gridDim.x * blockDim.x;
    __nv_bfloat16 z = __float2bfloat16(0.f);
    for (int k = i; k < 2 * 128 * 1024; k += st) { g_h0s[0][k] = z; g_h1s[0][k] = z; }
    for (int k = i; k < TT + 2; k += st) g_cnt[k] = 0;
}
__global__ void prep_split_x(const float* __restrict__ x) {
    size_t i = (size_t)blockIdx.x * blockDim.x + threadIdx.x;
    size_t st = (size_t)gridDim.x * blockDim.x;
    const size_t N = (size_t)64 * TT * 1024;
    for (size_t k = i; k < N; k += st) {
        float v = x[k];
        __nv_bfloat16 hi = __float2bfloat16(v);
        __nv_bfloat16 lo = __float2bfloat16(v - __bfloat162float(hi));
        size_t b = k >> 19, rest = k & ((1u << 19) - 1);   // T*H = 2^19
        g_xs[b * (size_t)(TT * 1024) + rest] = hi;
        g_xs[(b + 64) * (size_t)(TT * 1024) + rest] = lo;
    }
}

// ---------------------------------------------------------------------------
__global__ void __launch_bounds__(THREADS, 1)
rnn_mma_kernel(const float* __restrict__ W0, const float* __restrict__ b0,
               const float* __restrict__ W1, const float* __restrict__ b1,
               float* __restrict__ out) {
    extern __shared__ char smem[];
    const uint32_t sb = smem_u32(smem);
    float* stage = (float*)(smem + STAGE_OFF);
    const int tid = threadIdx.x, w = tid >> 5, lane = tid & 31;
    const int mg = w & 3, kh = w >> 2;
    const int cta = blockIdx.x, layer = cta >> 6, jcta = (cta & 63) * NCOL;
    const float* Wg   = layer ? W1 : W0;
    const float* bias = layer ? b1 : b0;

    // one-time: split W into SMEM, layout [n][k] bf16, row stride 4112B
    for (int i = tid; i < KDIM * NCOL; i += THREADS) {
        int k = i >> 4, n = i & 15;
        float v = Wg[(size_t)k * 1024 + jcta + n];
        __nv_bfloat16 hi = __float2bfloat16(v);
        __nv_bfloat16 lo = __float2bfloat16(v - __bfloat162float(hi));
        *(__nv_bfloat16*)(smem + WH_OFF + n * W_STRIDE + k * 2) = hi;
        *(__nv_bfloat16*)(smem + WL_OFF + n * W_STRIDE + k * 2) = lo;
    }

    // per-thread epilogue constants
    const int eb = tid >> 2, en0 = (tid & 3) * 4;
    float bv[4];
#pragma unroll
    for (int q = 0; q < 4; q++) bv[q] = bias[jcta + en0 + q];

    // mma fragment address bases (per warp: mg = m-group, kh = k-half)
    const uint32_t a_base = sb + A_OFF + (uint32_t)(32 * mg + (lane & 15)) * A_STRIDE
                          + (uint32_t)(lane >> 4) * 16 + (uint32_t)kh * 128;
    const int bn = (lane & 7) + ((lane >> 4) << 3);
    const uint32_t bh_base = sb + WH_OFF + (uint32_t)bn * W_STRIDE
                           + (uint32_t)((lane >> 3) & 1) * 16 + (uint32_t)kh * 128;
    const uint32_t bl_base = bh_base + (WL_OFF - WH_OFF);

    // cp.async mapping: each thread loads 8 rows (rb + 16j), 16B segment seg
    const int seg = tid & 15, rb = tid >> 4;

    const size_t FSOFF = (size_t)64 * TT * HH;
    __syncthreads();

    for (int p = 0; p <= TT; p++) {
        const bool active = layer ? (p >= 1) : (p < TT);
        if (active) {
            const int t = layer ? (p - 1) : p;
            const __nv_bfloat16* s0;
            const __nv_bfloat16* s1;
            size_t rst1;
            if (layer) { s0 = g_h1s[(p + 1) & 1]; s1 = g_h0s[(p + 1) & 1]; rst1 = 1024; }
            else       { s0 = g_h0s[(p + 1) & 1]; s1 = g_xs + (size_t)t * 1024; rst1 = (size_t)TT * 1024; }

            float acc[2][2][2][4];
#pragma unroll
            for (int i = 0; i < 32; i++) (&acc[0][0][0][0])[i] = 0.f;

            // prologue: stage chunk 0 (always from s0, k<1024)
            {
                const uint32_t db0 = sb + A_OFF + (uint32_t)rb * A_STRIDE + seg * 16;
                const __nv_bfloat16* sp = s0 + (size_t)rb * 1024 + seg * 8;
#pragma unroll
                for (int j = 0; j < 8; j++)
                    cp16(db0 + j * 16 * A_STRIDE, sp + (size_t)16 * j * 1024);
                cp_commit();
            }

            for (int c = 0; c < 16; c++) {
                if (c + 1 < 16) {
                    const int kb = (c + 1) * 128;
                    const __nv_bfloat16* srcb;
                    size_t rst;
                    if (kb < 1024) { srcb = s0 + kb; rst = 1024; }
                    else           { srcb = s1 + (kb - 1024); rst = rst1; }
                    const uint32_t db = sb + A_OFF + (uint32_t)((c + 1) & 1) * A_BUF
                                      + (uint32_t)rb * A_STRIDE + seg * 16;
                    const __nv_bfloat16* sp = srcb + (size_t)rb * rst + seg * 8;
#pragma unroll
                    for (int j = 0; j < 8; j++)
                        cp16(db + j * 16 * A_STRIDE, sp + (size_t)16 * j * rst);
                    cp_commit();
                    cp_wait<1>();
                } else {
                    cp_wait<0>();
                }
                __syncthreads();   // chunk c data visible to all warps

                {
                    const uint32_t ab = a_base + (uint32_t)(c & 1) * A_BUF;
                    const uint32_t bo = (uint32_t)c * 256;
#pragma unroll
                    for (int s = 0; s < 4; s++) {
                        uint32_t A0[4], A1[4], BH[4], BL[4];
                        ldsm4(A0, ab + s * 32);
                        ldsm4(A1, ab + 16 * A_STRIDE + s * 32);
                        ldsm4(BH, bh_base + bo + s * 32);
                        ldsm4(BL, bl_base + bo + s * 32);
                        mma16816(acc[0][0][0], A0, BH[0], BH[1]);
                        mma16816(acc[0][1][0], A0, BH[2], BH[3]);
                        mma16816(acc[1][0][0], A1, BH[0], BH[1]);
                        mma16816(acc[1][1][0], A1, BH[2], BH[3]);
                        mma16816(acc[0][0][1], A0, BL[0], BL[1]);
                        mma16816(acc[0][1][1], A0, BL[2], BL[3]);
                        mma16816(acc[1][0][1], A1, BL[0], BL[1]);
                        mma16816(acc[1][1][1], A1, BL[2], BL[3]);
                    }
                }
                __syncthreads();   // all warps done with buffer c&1
            }

            // write C fragments (hi+lo W splits pre-summed) to stage[kh]
            {
                const int r0 = 32 * mg + (lane >> 2);
                const int cc = 2 * (lane & 3);
                float* stg = stage + kh * (128 * 20);
#pragma unroll
                for (int mt = 0; mt < 2; mt++)
#pragma unroll
                    for (int nt = 0; nt < 2; nt++) {
                        const float* c0 = acc[mt][nt][0];
                        const float* c1 = acc[mt][nt][1];
                        const int col = 8 * nt + cc;
                        stg[(r0 + 16 * mt) * 20 + col]         = c0[0] + c1[0];
                        stg[(r0 + 16 * mt) * 20 + col + 1]     = c0[1] + c1[1];
                        stg[(r0 + 16 * mt + 8) * 20 + col]     = c0[2] + c1[2];
                        stg[(r0 + 16 * mt + 8) * 20 + col + 1] = c0[3] + c1[3];
                    }
            }
            __syncthreads();

            // combine k-halves and hi/lo A rows, bias, tanh, split-store h
            {
                float4 vh0 = *(float4*)&stage[eb * 20 + en0];
                float4 vh1 = *(float4*)&stage[128 * 20 + eb * 20 + en0];
                float4 vl0 = *(float4*)&stage[(eb + 64) * 20 + en0];
                float4 vl1 = *(float4*)&stage[128 * 20 + (eb + 64) * 20 + en0];
                float h[4];
                h[0] = tanhf(vh0.x + vh1.x + vl0.x + vl1.x + bv[0]);
                h[1] = tanhf(vh0.y + vh1.y + vl0.y + vl1.y + bv[1]);
                h[2] = tanhf(vh0.z + vh1.z + vl0.z + vl1.z + bv[2]);
                h[3] = tanhf(vh0.w + vh1.w + vl0.w + vl1.w + bv[3]);

                uint32_t hw[2], lw[2];
#pragma unroll
                for (int q = 0; q < 2; q++) {
                    __nv_bfloat16 h0 = __float2bfloat16(h[2 * q]);
                    __nv_bfloat16 h1 = __float2bfloat16(h[2 * q + 1]);
                    __nv_bfloat16 l0 = __float2bfloat16(h[2 * q] - __bfloat162float(h0));
                    __nv_bfloat16 l1 = __float2bfloat16(h[2 * q + 1] - __bfloat162float(h1));
                    hw[q] = (uint32_t)*(uint16_t*)&h0 | ((uint32_t)*(uint16_t*)&h1 << 16);
                    lw[q] = (uint32_t)*(uint16_t*)&l0 | ((uint32_t)*(uint16_t*)&l1 << 16);
                }
                __nv_bfloat16* hp = layer ? g_h1s[p & 1] : g_h0s[p & 1];
                __stcg((uint2*)(hp + (size_t)eb * 1024 + jcta + en0), make_uint2(hw[0], hw[1]));
                __stcg((uint2*)(hp + (size_t)(eb + 64) * 1024 + jcta + en0), make_uint2(lw[0], lw[1]));

                float4 of = make_float4(h[0], h[1], h[2], h[3]);
                if (layer) {
                    *(float4*)(out + ((size_t)eb * TT + t) * HH + jcta + en0) = of;
                    if (t == TT - 1)
                        *(float4*)(out + FSOFF + (size_t)eb * 2048 + 1024 + jcta + en0) = of;
                } else if (p == TT - 1) {
                    *(float4*)(out + FSOFF + (size_t)eb * 2048 + jcta + en0) = of;
                }
            }
        }

        // ---- grid barrier: per-phase counter ----
        __threadfence();
        __syncthreads();
        if (tid == 0) {
            atomicAdd(&g_cnt[p], 1);
            volatile int* cp = (volatile int*)&g_cnt[p];
            while (*cp < NCTA) { __nanosleep(32); }
        }
        __syncthreads();
    }
}

// ---------------------------------------------------------------------------
extern "C" void kernel_launch(void* const* d_in, const int* in_sizes, int n_in,
                              void* d_out, int out_size) {
    const float* x  = (const float*)d_in[0];
    const float* W0 = (const float*)d_in[1];
    const float* b0 = (const float*)d_in[2];
    const float* W1 = (const float*)d_in[3];
    const float* b1 = (const float*)d_in[4];
    float* out = (float*)d_out;

    cudaFuncSetAttribute(rnn_mma_kernel,
                         cudaFuncAttributeMaxDynamicSharedMemorySize, SMEM_BYTES);
    prep_state<<<64, 256>>>();
    prep_split_x<<<256, 256>>>(x);
    rnn_mma_kernel<<<NCTA, THREADS, SMEM_BYTES>>>(W0, b0, W1, b1, out);
}

// round 7
// speedup vs baseline: 3.5000x; 1.1462x over previous
#include <cuda_runtime.h>
#include <cuda_bf16.h>
#include <cstdint>

#define TT 512
#define HH 1024
#define KDIM 2048
#define NCOL 16
#define THREADS 256
#define NCTA 128

// smem byte offsets
#define W_STRIDE 4112            // 2048 bf16 + 16B pad per n-row
#define WH_OFF 0                 // 16 * 4112 = 65792
#define WL_OFF 65792
#define A_OFF  131584
#define A_STRIDE 272             // 128 bf16 chunk + 16B pad per A row
#define A_BUF  34816             // 128 rows * 272
#define STAGE_OFF 201216         // 2 * 128 * 20 * 4 = 20480
#define SMEM_BYTES 221696

__device__ __nv_bfloat16 g_xs[(size_t)128 * TT * 1024];   // x split planes: b<64 hi, b+64 lo
__device__ __nv_bfloat16 g_h0s[2][128 * 1024];
__device__ __nv_bfloat16 g_h1s[2][128 * 1024];
__device__ int g_cnt[TT + 2];

// ---------------------------------------------------------------------------
__device__ __forceinline__ uint32_t smem_u32(const void* p) {
    uint32_t a;
    asm("{ .reg .u64 t; cvta.to.shared.u64 t, %1; cvt.u32.u64 %0, t; }" : "=r"(a) : "l"(p));
    return a;
}
__device__ __forceinline__ void cp16(uint32_t d, const void* s) {
    asm volatile("cp.async.cg.shared.global [%0], [%1], 16;" :: "r"(d), "l"(s));
}
__device__ __forceinline__ void cp_commit() { asm volatile("cp.async.commit_group;"); }
template <int N>
__device__ __forceinline__ void cp_wait() { asm volatile("cp.async.wait_group %0;" :: "n"(N)); }

__device__ __forceinline__ void ldsm4(uint32_t* r, uint32_t addr) {
    asm volatile("ldmatrix.sync.aligned.m8n8.x4.shared.b16 {%0,%1,%2,%3}, [%4];"
        : "=r"(r[0]), "=r"(r[1]), "=r"(r[2]), "=r"(r[3]) : "r"(addr));
}
__device__ __forceinline__ void mma16816(float* c, const uint32_t* a, uint32_t b0, uint32_t b1) {
    asm volatile("mma.sync.aligned.m16n8k16.row.col.f32.bf16.bf16.f32 "
        "{%0,%1,%2,%3}, {%4,%5,%6,%7}, {%8,%9}, {%0,%1,%2,%3};"
        : "+f"(c[0]), "+f"(c[1]), "+f"(c[2]), "+f"(c[3])
        : "r"(a[0]), "r"(a[1]), "r"(a[2]), "r"(a[3]), "r"(b0), "r"(b1));
}

// ---------------------------------------------------------------------------
// Single prep kernel: zero states/counters + split x into bf16 hi/lo planes.
__global__ void prep_all(const float* __restrict__ x) {
    size_t i = (size_t)blockIdx.x * blockDim.x + threadIdx.x;
    size_t st = (size_t)gridDim.x * blockDim.x;
    __nv_bfloat16 z = __float2bfloat16(0.f);
    for (size_t k = i; k < 2 * 128 * 1024; k += st) { g_h0s[0][k] = z; g_h1s[0][k] = z; }
    for (size_t k = i; k < TT + 2; k += st) g_cnt[k] = 0;
    const size_t N = (size_t)64 * TT * 1024;
    for (size_t k = i; k < N; k += st) {
        float v = x[k];
        __nv_bfloat16 hi = __float2bfloat16(v);
        __nv_bfloat16 lo = __float2bfloat16(v - __bfloat162float(hi));
        size_t b = k >> 19, rest = k & ((1u << 19) - 1);   // T*H = 2^19
        g_xs[b * (size_t)(TT * 1024) + rest] = hi;
        g_xs[(b + 64) * (size_t)(TT * 1024) + rest] = lo;
    }
}

// ---------------------------------------------------------------------------
__global__ void __launch_bounds__(THREADS, 1)
rnn_mma_kernel(const float* __restrict__ W0, const float* __restrict__ b0,
               const float* __restrict__ W1, const float* __restrict__ b1,
               float* __restrict__ out) {
    extern __shared__ char smem[];
    const uint32_t sb = smem_u32(smem);
    float* stage = (float*)(smem + STAGE_OFF);
    const int tid = threadIdx.x, w = tid >> 5, lane = tid & 31;
    const int mg = w & 3, kh = w >> 2;
    const int cta = blockIdx.x, layer = cta >> 6, jcta = (cta & 63) * NCOL;
    const float* Wg   = layer ? W1 : W0;
    const float* bias = layer ? b1 : b0;

    // one-time: split W into SMEM, layout [n][k] bf16, row stride 4112B
    for (int i = tid; i < KDIM * NCOL; i += THREADS) {
        int k = i >> 4, n = i & 15;
        float v = Wg[(size_t)k * 1024 + jcta + n];
        __nv_bfloat16 hi = __float2bfloat16(v);
        __nv_bfloat16 lo = __float2bfloat16(v - __bfloat162float(hi));
        *(__nv_bfloat16*)(smem + WH_OFF + n * W_STRIDE + k * 2) = hi;
        *(__nv_bfloat16*)(smem + WL_OFF + n * W_STRIDE + k * 2) = lo;
    }

    // per-thread epilogue constants
    const int eb = tid >> 2, en0 = (tid & 3) * 4;
    float bv[4];
#pragma unroll
    for (int q = 0; q < 4; q++) bv[q] = bias[jcta + en0 + q];

    // fragment address bases: warp (mg, kh) owns hi m-tile rows [16mg,16mg+16)
    // and lo m-tile rows [64+16mg, 64+16mg+16), k-half kh of each 128-k chunk.
    const uint32_t a0_base = sb + A_OFF + (uint32_t)(16 * mg + (lane & 15)) * A_STRIDE
                           + (uint32_t)(lane >> 4) * 16 + (uint32_t)kh * 128;
    const uint32_t a1_base = a0_base + 64 * A_STRIDE;
    const int bn = (lane & 7) + ((lane >> 4) << 3);
    const uint32_t bh_base = sb + WH_OFF + (uint32_t)bn * W_STRIDE
                           + (uint32_t)((lane >> 3) & 1) * 16 + (uint32_t)kh * 128;
    const uint32_t bl_base = bh_base + (WL_OFF - WH_OFF);

    // cp.async mapping: each thread loads 8 rows (rb + 16j), 16B segment seg
    const int seg = tid & 15, rb = tid >> 4;

    const size_t FSOFF = (size_t)64 * TT * HH;
    __syncthreads();

    for (int p = 0; p <= TT; p++) {
        const bool active = layer ? (p >= 1) : (p < TT);
        if (active) {
            const int t = layer ? (p - 1) : p;
            const __nv_bfloat16* s0;
            const __nv_bfloat16* s1;
            size_t rst1;
            if (layer) { s0 = g_h1s[(p + 1) & 1]; s1 = g_h0s[(p + 1) & 1]; rst1 = 1024; }
            else       { s0 = g_h0s[(p + 1) & 1]; s1 = g_xs + (size_t)t * 1024; rst1 = (size_t)TT * 1024; }

            float accHH[2][4], accLH[2][4], accHL[2][4];
#pragma unroll
            for (int i = 0; i < 8; i++) {
                (&accHH[0][0])[i] = 0.f; (&accLH[0][0])[i] = 0.f; (&accHL[0][0])[i] = 0.f;
            }

            // prologue: stage chunk 0 (always from s0, k<1024)
            {
                const uint32_t db0 = sb + A_OFF + (uint32_t)rb * A_STRIDE + seg * 16;
                const __nv_bfloat16* sp = s0 + (size_t)rb * 1024 + seg * 8;
#pragma unroll
                for (int j = 0; j < 8; j++)
                    cp16(db0 + j * 16 * A_STRIDE, sp + (size_t)16 * j * 1024);
                cp_commit();
            }

            for (int c = 0; c < 16; c++) {
                if (c + 1 < 16) {
                    const int kb = (c + 1) * 128;
                    const __nv_bfloat16* srcb;
                    size_t rst;
                    if (kb < 1024) { srcb = s0 + kb; rst = 1024; }
                    else           { srcb = s1 + (kb - 1024); rst = rst1; }
                    const uint32_t db = sb + A_OFF + (uint32_t)((c + 1) & 1) * A_BUF
                                      + (uint32_t)rb * A_STRIDE + seg * 16;
                    const __nv_bfloat16* sp = srcb + (size_t)rb * rst + seg * 8;
#pragma unroll
                    for (int j = 0; j < 8; j++)
                        cp16(db + j * 16 * A_STRIDE, sp + (size_t)16 * j * rst);
                    cp_commit();
                    cp_wait<1>();
                } else {
                    cp_wait<0>();
                }
                __syncthreads();   // chunk c data visible to all warps

                {
                    const uint32_t abo = (uint32_t)(c & 1) * A_BUF;
                    const uint32_t bo = (uint32_t)c * 256;
#pragma unroll
                    for (int s = 0; s < 4; s++) {
                        uint32_t A0[4], A1[4], BH[4], BL[4];
                        ldsm4(A0, a0_base + abo + s * 32);
                        ldsm4(A1, a1_base + abo + s * 32);
                        ldsm4(BH, bh_base + bo + s * 32);
                        ldsm4(BL, bl_base + bo + s * 32);
                        mma16816(accHH[0], A0, BH[0], BH[1]);   // ah*wh
                        mma16816(accHH[1], A0, BH[2], BH[3]);
                        mma16816(accLH[0], A1, BH[0], BH[1]);   // al*wh
                        mma16816(accLH[1], A1, BH[2], BH[3]);
                        mma16816(accHL[0], A0, BL[0], BL[1]);   // ah*wl
                        mma16816(accHL[1], A0, BL[2], BL[3]);
                    }
                }
                if (c + 1 < 16) __syncthreads();   // all warps done with buffer c&1
            }

            // write C fragments to stage[kh]: hi rows get HH+HL, lo rows get LH
            {
                const int r0 = 16 * mg + (lane >> 2);
                const int cc = 2 * (lane & 3);
                float* stg = stage + kh * (128 * 20);
#pragma unroll
                for (int nt = 0; nt < 2; nt++) {
                    const int col = 8 * nt + cc;
                    stg[r0 * 20 + col]            = accHH[nt][0] + accHL[nt][0];
                    stg[r0 * 20 + col + 1]        = accHH[nt][1] + accHL[nt][1];
                    stg[(r0 + 8) * 20 + col]      = accHH[nt][2] + accHL[nt][2];
                    stg[(r0 + 8) * 20 + col + 1]  = accHH[nt][3] + accHL[nt][3];
                    stg[(64 + r0) * 20 + col]     = accLH[nt][0];
                    stg[(64 + r0) * 20 + col + 1] = accLH[nt][1];
                    stg[(72 + r0) * 20 + col]     = accLH[nt][2];
                    stg[(72 + r0) * 20 + col + 1] = accLH[nt][3];
                }
            }
            __syncthreads();

            // combine k-halves and hi/lo planes, bias, tanh, split-store h
            {
                float4 vh0 = *(float4*)&stage[eb * 20 + en0];
                float4 vh1 = *(float4*)&stage[128 * 20 + eb * 20 + en0];
                float4 vl0 = *(float4*)&stage[(eb + 64) * 20 + en0];
                float4 vl1 = *(float4*)&stage[128 * 20 + (eb + 64) * 20 + en0];
                float h[4];
                h[0] = tanhf(vh0.x + vh1.x + vl0.x + vl1.x + bv[0]);
                h[1] = tanhf(vh0.y + vh1.y + vl0.y + vl1.y + bv[1]);
                h[2] = tanhf(vh0.z + vh1.z + vl0.z + vl1.z + bv[2]);
                h[3] = tanhf(vh0.w + vh1.w + vl0.w + vl1.w + bv[3]);

                uint32_t hw[2], lw[2];
#pragma unroll
                for (int q = 0; q < 2; q++) {
                    __nv_bfloat16 h0 = __float2bfloat16(h[2 * q]);
                    __nv_bfloat16 h1 = __float2bfloat16(h[2 * q + 1]);
                    __nv_bfloat16 l0 = __float2bfloat16(h[2 * q] - __bfloat162float(h0));
                    __nv_bfloat16 l1 = __float2bfloat16(h[2 * q + 1] - __bfloat162float(h1));
                    hw[q] = (uint32_t)*(uint16_t*)&h0 | ((uint32_t)*(uint16_t*)&h1 << 16);
                    lw[q] = (uint32_t)*(uint16_t*)&l0 | ((uint32_t)*(uint16_t*)&l1 << 16);
                }
                __nv_bfloat16* hp = layer ? g_h1s[p & 1] : g_h0s[p & 1];
                __stcg((uint2*)(hp + (size_t)eb * 1024 + jcta + en0), make_uint2(hw[0], hw[1]));
                __stcg((uint2*)(hp + (size_t)(eb + 64) * 1024 + jcta + en0), make_uint2(lw[0], lw[1]));

                float4 of = make_float4(h[0], h[1], h[2], h[3]);
                if (layer) {
                    *(float4*)(out + ((size_t)eb * TT + t) * HH + jcta + en0) = of;
                    if (t == TT - 1)
                        *(float4*)(out + FSOFF + (size_t)eb * 2048 + 1024 + jcta + en0) = of;
                } else if (p == TT - 1) {
                    *(float4*)(out + FSOFF + (size_t)eb * 2048 + jcta + en0) = of;
                }
            }
        }

        // ---- grid barrier: per-phase counter ----
        __threadfence();
        __syncthreads();
        if (tid == 0) {
            atomicAdd(&g_cnt[p], 1);
            volatile int* cp = (volatile int*)&g_cnt[p];
            while (*cp < NCTA) { __nanosleep(32); }
        }
        __syncthreads();
    }
}

// ---------------------------------------------------------------------------
extern "C" void kernel_launch(void* const* d_in, const int* in_sizes, int n_in,
                              void* d_out, int out_size) {
    const float* x  = (const float*)d_in[0];
    const float* W0 = (const float*)d_in[1];
    const float* b0 = (const float*)d_in[2];
    const float* W1 = (const float*)d_in[3];
    const float* b1 = (const float*)d_in[4];
    float* out = (float*)d_out;

    cudaFuncSetAttribute(rnn_mma_kernel,
                         cudaFuncAttributeMaxDynamicSharedMemorySize, SMEM_BYTES);
    prep_all<<<512, 256>>>(x);
    rnn_mma_kernel<<<NCTA, THREADS, SMEM_BYTES>>>(W0, b0, W1, b1, out);
}

// round 8
// speedup vs baseline: 3.5891x; 1.0255x over previous
#include <cuda_runtime.h>
#include <cuda_bf16.h>
#include <cstdint>

#define TT 512
#define HH 1024
#define KDIM 2048
#define NCOL 16
#define THREADS 512
#define NCTA 128

// smem byte offsets
#define W_STRIDE 4112            // 2048 bf16 + 16B pad per n-row
#define WH_OFF 0                 // 16 * 4112 = 65792
#define WL_OFF 65792
#define A_OFF  131584
#define A_STRIDE 272             // 128 bf16 chunk + 16B pad per A row
#define A_BUF  34816             // 128 rows * 272
#define STAGE_OFF A_OFF          // overlaid on A buffers (safe: see sync notes)
#define SMEM_BYTES 201216

__device__ __nv_bfloat16 g_xs[(size_t)128 * TT * 1024];   // x split planes: b<64 hi, b+64 lo
__device__ __nv_bfloat16 g_h0s[2][128 * 1024];
__device__ __nv_bfloat16 g_h1s[2][128 * 1024];
__device__ int g_cnt[TT + 2];

// ---------------------------------------------------------------------------
__device__ __forceinline__ uint32_t smem_u32(const void* p) {
    uint32_t a;
    asm("{ .reg .u64 t; cvta.to.shared.u64 t, %1; cvt.u32.u64 %0, t; }" : "=r"(a) : "l"(p));
    return a;
}
__device__ __forceinline__ void cp16(uint32_t d, const void* s) {
    asm volatile("cp.async.cg.shared.global [%0], [%1], 16;" :: "r"(d), "l"(s));
}
__device__ __forceinline__ void cp_commit() { asm volatile("cp.async.commit_group;"); }
template <int N>
__device__ __forceinline__ void cp_wait() { asm volatile("cp.async.wait_group %0;" :: "n"(N)); }

__device__ __forceinline__ void ldsm4(uint32_t* r, uint32_t addr) {
    asm volatile("ldmatrix.sync.aligned.m8n8.x4.shared.b16 {%0,%1,%2,%3}, [%4];"
        : "=r"(r[0]), "=r"(r[1]), "=r"(r[2]), "=r"(r[3]) : "r"(addr));
}
__device__ __forceinline__ void mma16816(float* c, const uint32_t* a, uint32_t b0, uint32_t b1) {
    asm volatile("mma.sync.aligned.m16n8k16.row.col.f32.bf16.bf16.f32 "
        "{%0,%1,%2,%3}, {%4,%5,%6,%7}, {%8,%9}, {%0,%1,%2,%3};"
        : "+f"(c[0]), "+f"(c[1]), "+f"(c[2]), "+f"(c[3])
        : "r"(a[0]), "r"(a[1]), "r"(a[2]), "r"(a[3]), "r"(b0), "r"(b1));
}

// ---------------------------------------------------------------------------
// Single prep kernel: zero states/counters + split x into bf16 hi/lo planes.
__global__ void prep_all(const float* __restrict__ x) {
    size_t i = (size_t)blockIdx.x * blockDim.x + threadIdx.x;
    size_t st = (size_t)gridDim.x * blockDim.x;
    __nv_bfloat16 z = __float2bfloat16(0.f);
    for (size_t k = i; k < 2 * 128 * 1024; k += st) { g_h0s[0][k] = z; g_h1s[0][k] = z; }
    for (size_t k = i; k < TT + 2; k += st) g_cnt[k] = 0;
    const size_t N = (size_t)64 * TT * 1024;
    for (size_t k = i; k < N; k += st) {
        float v = x[k];
        __nv_bfloat16 hi = __float2bfloat16(v);
        __nv_bfloat16 lo = __float2bfloat16(v - __bfloat162float(hi));
        size_t b = k >> 19, rest = k & ((1u << 19) - 1);   // T*H = 2^19
        g_xs[b * (size_t)(TT * 1024) + rest] = hi;
        g_xs[(b + 64) * (size_t)(TT * 1024) + rest] = lo;
    }
}

// ---------------------------------------------------------------------------
__global__ void __launch_bounds__(THREADS, 1)
rnn_mma_kernel(const float* __restrict__ W0, const float* __restrict__ b0,
               const float* __restrict__ W1, const float* __restrict__ b1,
               float* __restrict__ out) {
    extern __shared__ char smem[];
    const uint32_t sb = smem_u32(smem);
    float* stage = (float*)(smem + STAGE_OFF);   // 4 planes x 128 rows x 20 floats
    const int tid = threadIdx.x, w = tid >> 5, lane = tid & 31;
    const int mg = w & 3, kq = w >> 2;           // m-group 0..3, k-quarter 0..3
    const int cta = blockIdx.x, layer = cta >> 6, jcta = (cta & 63) * NCOL;
    const float* Wg   = layer ? W1 : W0;
    const float* bias = layer ? b1 : b0;

    // one-time: split W into SMEM, layout [n][k] bf16, row stride 4112B
    for (int i = tid; i < KDIM * NCOL; i += THREADS) {
        int k = i >> 4, n = i & 15;
        float v = Wg[(size_t)k * 1024 + jcta + n];
        __nv_bfloat16 hi = __float2bfloat16(v);
        __nv_bfloat16 lo = __float2bfloat16(v - __bfloat162float(hi));
        *(__nv_bfloat16*)(smem + WH_OFF + n * W_STRIDE + k * 2) = hi;
        *(__nv_bfloat16*)(smem + WL_OFF + n * W_STRIDE + k * 2) = lo;
    }

    // per-thread epilogue constants: thread -> (batch eb, col pair en0)
    const int eb = tid >> 3, en0 = (tid & 7) * 2;
    float bv0 = bias[jcta + en0], bv1 = bias[jcta + en0 + 1];

    // fragment address bases: warp (mg, kq) owns hi m-tile rows [16mg,16mg+16)
    // and lo m-tile rows [64+16mg, ...), k-quarter kq (32 k) of each 128-k chunk.
    const uint32_t a0_base = sb + A_OFF + (uint32_t)(16 * mg + (lane & 15)) * A_STRIDE
                           + (uint32_t)(lane >> 4) * 16 + (uint32_t)kq * 64;
    const uint32_t a1_base = a0_base + 64 * A_STRIDE;
    const int bn = (lane & 7) + ((lane >> 4) << 3);
    const uint32_t bh_base = sb + WH_OFF + (uint32_t)bn * W_STRIDE
                           + (uint32_t)((lane >> 3) & 1) * 16 + (uint32_t)kq * 64;
    const uint32_t bl_base = bh_base + (WL_OFF - WH_OFF);

    // cp.async mapping: thread loads 4 rows (rb + 32j), 16B segment seg
    const int seg = tid & 15, rb = tid >> 4;     // rb 0..31

    const size_t FSOFF = (size_t)64 * TT * HH;
    __syncthreads();

    for (int p = 0; p <= TT; p++) {
        const bool active = layer ? (p >= 1) : (p < TT);
        if (active) {
            const int t = layer ? (p - 1) : p;
            const __nv_bfloat16* s0;
            const __nv_bfloat16* s1;
            size_t rst1;
            if (layer) { s0 = g_h1s[(p + 1) & 1]; s1 = g_h0s[(p + 1) & 1]; rst1 = 1024; }
            else       { s0 = g_h0s[(p + 1) & 1]; s1 = g_xs + (size_t)t * 1024; rst1 = (size_t)TT * 1024; }

            float accHH[2][4], accLH[2][4], accHL[2][4];
#pragma unroll
            for (int i = 0; i < 8; i++) {
                (&accHH[0][0])[i] = 0.f; (&accLH[0][0])[i] = 0.f; (&accHL[0][0])[i] = 0.f;
            }

            // prologue: stage chunk 0 (always from s0, k<1024)
            {
                const uint32_t db0 = sb + A_OFF + (uint32_t)rb * A_STRIDE + seg * 16;
                const __nv_bfloat16* sp = s0 + (size_t)rb * 1024 + seg * 8;
#pragma unroll
                for (int j = 0; j < 4; j++)
                    cp16(db0 + j * 32 * A_STRIDE, sp + (size_t)32 * j * 1024);
                cp_commit();
            }

            for (int c = 0; c < 16; c++) {
                if (c + 1 < 16) {
                    const int kb = (c + 1) * 128;
                    const __nv_bfloat16* srcb;
                    size_t rst;
                    if (kb < 1024) { srcb = s0 + kb; rst = 1024; }
                    else           { srcb = s1 + (kb - 1024); rst = rst1; }
                    const uint32_t db = sb + A_OFF + (uint32_t)((c + 1) & 1) * A_BUF
                                      + (uint32_t)rb * A_STRIDE + seg * 16;
                    const __nv_bfloat16* sp = srcb + (size_t)rb * rst + seg * 8;
#pragma unroll
                    for (int j = 0; j < 4; j++)
                        cp16(db + j * 32 * A_STRIDE, sp + (size_t)32 * j * rst);
                    cp_commit();
                    cp_wait<1>();
                } else {
                    cp_wait<0>();
                }
                __syncthreads();   // chunk c data visible to all warps

                {
                    const uint32_t abo = (uint32_t)(c & 1) * A_BUF;
                    const uint32_t bo = (uint32_t)c * 256;
#pragma unroll
                    for (int s = 0; s < 2; s++) {
                        uint32_t A0[4], A1[4], BH[4], BL[4];
                        ldsm4(A0, a0_base + abo + s * 32);
                        ldsm4(A1, a1_base + abo + s * 32);
                        ldsm4(BH, bh_base + bo + s * 32);
                        ldsm4(BL, bl_base + bo + s * 32);
                        mma16816(accHH[0], A0, BH[0], BH[1]);   // ah*wh
                        mma16816(accHH[1], A0, BH[2], BH[3]);
                        mma16816(accLH[0], A1, BH[0], BH[1]);   // al*wh
                        mma16816(accLH[1], A1, BH[2], BH[3]);
                        mma16816(accHL[0], A0, BL[0], BL[1]);   // ah*wl
                        mma16816(accHL[1], A0, BL[2], BL[3]);
                    }
                }
                __syncthreads();   // buffer reuse; at c=15 also guards stage overlay
            }

            // write C fragments to stage[kq]: hi rows get HH+HL, lo rows get LH
            {
                const int r0 = 16 * mg + (lane >> 2);
                const int cc = 2 * (lane & 3);
                float* stg = stage + kq * (128 * 20);
#pragma unroll
                for (int nt = 0; nt < 2; nt++) {
                    const int col = 8 * nt + cc;
                    stg[r0 * 20 + col]            = accHH[nt][0] + accHL[nt][0];
                    stg[r0 * 20 + col + 1]        = accHH[nt][1] + accHL[nt][1];
                    stg[(r0 + 8) * 20 + col]      = accHH[nt][2] + accHL[nt][2];
                    stg[(r0 + 8) * 20 + col + 1]  = accHH[nt][3] + accHL[nt][3];
                    stg[(64 + r0) * 20 + col]     = accLH[nt][0];
                    stg[(64 + r0) * 20 + col + 1] = accLH[nt][1];
                    stg[(72 + r0) * 20 + col]     = accLH[nt][2];
                    stg[(72 + r0) * 20 + col + 1] = accLH[nt][3];
                }
            }
            __syncthreads();

            // combine k-quarters and hi/lo planes, bias, tanh, split-store h
            {
                float s0v = bv0, s1v = bv1;
#pragma unroll
                for (int q = 0; q < 4; q++) {
                    const float* st0 = stage + q * (128 * 20) + eb * 20 + en0;
                    const float* st1 = stage + q * (128 * 20) + (eb + 64) * 20 + en0;
                    s0v += st0[0] + st1[0];
                    s1v += st0[1] + st1[1];
                }
                float h0f = tanhf(s0v), h1f = tanhf(s1v);

                __nv_bfloat16 h0 = __float2bfloat16(h0f);
                __nv_bfloat16 h1 = __float2bfloat16(h1f);
                __nv_bfloat16 l0 = __float2bfloat16(h0f - __bfloat162float(h0));
                __nv_bfloat16 l1 = __float2bfloat16(h1f - __bfloat162float(h1));
                uint32_t hw = (uint32_t)*(uint16_t*)&h0 | ((uint32_t)*(uint16_t*)&h1 << 16);
                uint32_t lw = (uint32_t)*(uint16_t*)&l0 | ((uint32_t)*(uint16_t*)&l1 << 16);

                __nv_bfloat16* hp = layer ? g_h1s[p & 1] : g_h0s[p & 1];
                __stcg((uint32_t*)(hp + (size_t)eb * 1024 + jcta + en0), hw);
                __stcg((uint32_t*)(hp + (size_t)(eb + 64) * 1024 + jcta + en0), lw);

                float2 of = make_float2(h0f, h1f);
                if (layer) {
                    *(float2*)(out + ((size_t)eb * TT + t) * HH + jcta + en0) = of;
                    if (t == TT - 1)
                        *(float2*)(out + FSOFF + (size_t)eb * 2048 + 1024 + jcta + en0) = of;
                } else if (p == TT - 1) {
                    *(float2*)(out + FSOFF + (size_t)eb * 2048 + jcta + en0) = of;
                }
            }
        }

        // ---- grid barrier: per-phase counter ----
        __threadfence();
        __syncthreads();
        if (tid == 0) {
            atomicAdd(&g_cnt[p], 1);
            volatile int* cp = (volatile int*)&g_cnt[p];
            while (*cp < NCTA) { __nanosleep(32); }
        }
        __syncthreads();
    }
}

// ---------------------------------------------------------------------------
extern "C" void kernel_launch(void* const* d_in, const int* in_sizes, int n_in,
                              void* d_out, int out_size) {
    const float* x  = (const float*)d_in[0];
    const float* W0 = (const float*)d_in[1];
    const float* b0 = (const float*)d_in[2];
    const float* W1 = (const float*)d_in[3];
    const float* b1 = (const float*)d_in[4];
    float* out = (float*)d_out;

    cudaFuncSetAttribute(rnn_mma_kernel,
                         cudaFuncAttributeMaxDynamicSharedMemorySize, SMEM_BYTES);
    prep_all<<<512, 256>>>(x);
    rnn_mma_kernel<<<NCTA, THREADS, SMEM_BYTES>>>(W0, b0, W1, b1, out);
}

// round 9
// speedup vs baseline: 5.2486x; 1.4624x over previous
#include <cuda_runtime.h>
#include <cuda_bf16.h>
#include <cstdint>

#define TT 512
#define HH 1024
#define KDIM 2048
#define NCOL 16
#define THREADS 512
#define NCTA 128

// smem byte offsets
#define W_STRIDE 4112            // 2048 bf16 + 16B pad per n-row
#define WH_OFF 0                 // 16 * 4112 = 65792
#define WL_OFF 65792
#define A_OFF  131584            // 3 buffers x 32768 B (128 rows x 256 B, XOR-swizzled)
#define A_BUF  32768
#define STAGE_OFF A_OFF          // overlaid on A buffers (guarded by post-loop sync)
#define SMEM_BYTES 229888

__device__ __nv_bfloat16 g_xs[(size_t)128 * TT * 1024];   // x split planes: b<64 hi, b+64 lo
__device__ __nv_bfloat16 g_h0s[2][128 * 1024];
__device__ __nv_bfloat16 g_h1s[2][128 * 1024];
__device__ int g_cnt[TT + 2];

// ---------------------------------------------------------------------------
__device__ __forceinline__ uint32_t smem_u32(const void* p) {
    uint32_t a;
    asm("{ .reg .u64 t; cvta.to.shared.u64 t, %1; cvt.u32.u64 %0, t; }" : "=r"(a) : "l"(p));
    return a;
}
__device__ __forceinline__ void cp16(uint32_t d, const void* s) {
    asm volatile("cp.async.cg.shared.global [%0], [%1], 16;" :: "r"(d), "l"(s));
}
__device__ __forceinline__ void cp_commit() { asm volatile("cp.async.commit_group;"); }
template <int N>
__device__ __forceinline__ void cp_wait() { asm volatile("cp.async.wait_group %0;" :: "n"(N)); }

__device__ __forceinline__ void ldsm4(uint32_t* r, uint32_t addr) {
    asm volatile("ldmatrix.sync.aligned.m8n8.x4.shared.b16 {%0,%1,%2,%3}, [%4];"
        : "=r"(r[0]), "=r"(r[1]), "=r"(r[2]), "=r"(r[3]) : "r"(addr));
}
__device__ __forceinline__ void mma16816(float* c, const uint32_t* a, uint32_t b0, uint32_t b1) {
    asm volatile("mma.sync.aligned.m16n8k16.row.col.f32.bf16.bf16.f32 "
        "{%0,%1,%2,%3}, {%4,%5,%6,%7}, {%8,%9}, {%0,%1,%2,%3};"
        : "+f"(c[0]), "+f"(c[1]), "+f"(c[2]), "+f"(c[3])
        : "r"(a[0]), "r"(a[1]), "r"(a[2]), "r"(a[3]), "r"(b0), "r"(b1));
}

// ---------------------------------------------------------------------------
// Single prep kernel: zero states/counters + split x into bf16 hi/lo planes.
__global__ void prep_all(const float* __restrict__ x) {
    size_t i = (size_t)blockIdx.x * blockDim.x + threadIdx.x;
    size_t st = (size_t)gridDim.x * blockDim.x;
    __nv_bfloat16 z = __float2bfloat16(0.f);
    for (size_t k = i; k < 2 * 128 * 1024; k += st) { g_h0s[0][k] = z; g_h1s[0][k] = z; }
    for (size_t k = i; k < TT + 2; k += st) g_cnt[k] = 0;
    const size_t N = (size_t)64 * TT * 1024;
    for (size_t k = i; k < N; k += st) {
        float v = x[k];
        __nv_bfloat16 hi = __float2bfloat16(v);
        __nv_bfloat16 lo = __float2bfloat16(v - __bfloat162float(hi));
        size_t b = k >> 19, rest = k & ((1u << 19) - 1);   // T*H = 2^19
        g_xs[b * (size_t)(TT * 1024) + rest] = hi;
        g_xs[(b + 64) * (size_t)(TT * 1024) + rest] = lo;
    }
}

// ---------------------------------------------------------------------------
__global__ void __launch_bounds__(THREADS, 1)
rnn_mma_kernel(const float* __restrict__ W0, const float* __restrict__ b0,
               const float* __restrict__ W1, const float* __restrict__ b1,
               float* __restrict__ out) {
    extern __shared__ char smem[];
    const uint32_t sb = smem_u32(smem);
    float* stage = (float*)(smem + STAGE_OFF);   // 4 planes x 128 rows x 20 floats
    const int tid = threadIdx.x, w = tid >> 5, lane = tid & 31;
    const int mg = w & 3, kq = w >> 2;           // m-group 0..3, k-quarter 0..3
    const int cta = blockIdx.x, layer = cta >> 6, jcta = (cta & 63) * NCOL;
    const float* Wg   = layer ? W1 : W0;
    const float* bias = layer ? b1 : b0;

    // one-time: split W into SMEM, layout [n][k] bf16, row stride 4112B
    for (int i = tid; i < KDIM * NCOL; i += THREADS) {
        int k = i >> 4, n = i & 15;
        float v = Wg[(size_t)k * 1024 + jcta + n];
        __nv_bfloat16 hi = __float2bfloat16(v);
        __nv_bfloat16 lo = __float2bfloat16(v - __bfloat162float(hi));
        *(__nv_bfloat16*)(smem + WH_OFF + n * W_STRIDE + k * 2) = hi;
        *(__nv_bfloat16*)(smem + WL_OFF + n * W_STRIDE + k * 2) = lo;
    }

    // per-thread epilogue constants: thread -> (batch eb, col pair en0)
    const int eb = tid >> 3, en0 = (tid & 7) * 2;
    float bv0 = bias[jcta + en0], bv1 = bias[jcta + en0 + 1];

    // A fragment addressing (XOR-swizzled, 256B rows):
    //   phys_off(row, log_chunk16B) = row*256 + ((log_chunk ^ (row & 7)) << 4)
    const int arow = 16 * mg + (lane & 15);
    const uint32_t row0_off = (uint32_t)arow << 8;
    const int c0log = kq * 4 + (lane >> 4);      // logical 16B-chunk base for s=0
    const int xorm = lane & 7;
    const int bn = (lane & 7) + ((lane >> 4) << 3);
    const uint32_t bh_base = sb + WH_OFF + (uint32_t)bn * W_STRIDE
                           + (uint32_t)((lane >> 3) & 1) * 16 + (uint32_t)kq * 64;
    const uint32_t bl_base = bh_base + (WL_OFF - WH_OFF);

    // cp.async mapping: thread -> (seg = logical chunk, rb = row base), rows rb+32j
    const int seg = tid & 15, rb = tid >> 4;     // rb 0..31
    const uint32_t dstbase = sb + A_OFF + ((uint32_t)rb << 8)
                           + (uint32_t)((seg ^ (rb & 7)) << 4);

    const size_t FSOFF = (size_t)64 * TT * HH;
    __syncthreads();

    for (int p = 0; p <= TT; p++) {
        const bool active = layer ? (p >= 1) : (p < TT);
        if (active) {
            const int t = layer ? (p - 1) : p;
            const __nv_bfloat16* s0;
            const __nv_bfloat16* s1;
            size_t rst1;
            if (layer) { s0 = g_h1s[(p + 1) & 1]; s1 = g_h0s[(p + 1) & 1]; rst1 = 1024; }
            else       { s0 = g_h0s[(p + 1) & 1]; s1 = g_xs + (size_t)t * 1024; rst1 = (size_t)TT * 1024; }

            float accHH[2][4], accLH[2][4], accHL[2][4];
#pragma unroll
            for (int i = 0; i < 8; i++) {
                (&accHH[0][0])[i] = 0.f; (&accLH[0][0])[i] = 0.f; (&accHL[0][0])[i] = 0.f;
            }

            // prologue: stage chunks 0 and 1 (both from s0, k<1024)
#pragma unroll
            for (int cc = 0; cc < 2; cc++) {
                const uint32_t db = dstbase + (uint32_t)cc * A_BUF;
                const __nv_bfloat16* sp = s0 + (size_t)rb * 1024 + cc * 128 + seg * 8;
#pragma unroll
                for (int j = 0; j < 4; j++)
                    cp16(db + j * 8192, sp + (size_t)32 * j * 1024);
                cp_commit();
            }

            for (int c = 0; c < 16; c++) {
                if (c < 15) cp_wait<1>(); else cp_wait<0>();
                __syncthreads();   // chunk c visible + chunk c-1 consumers done

                if (c + 2 < 16) {
                    const int kb = (c + 2) * 128;
                    const __nv_bfloat16* srcb;
                    size_t rst;
                    if (kb < 1024) { srcb = s0 + kb; rst = 1024; }
                    else           { srcb = s1 + (kb - 1024); rst = rst1; }
                    const uint32_t db = dstbase + (uint32_t)((c + 2) % 3) * A_BUF;
                    const __nv_bfloat16* sp = srcb + (size_t)rb * rst + seg * 8;
#pragma unroll
                    for (int j = 0; j < 4; j++)
                        cp16(db + j * 8192, sp + (size_t)32 * j * rst);
                    cp_commit();
                }

                {
                    const uint32_t abuf = sb + A_OFF + (uint32_t)(c % 3) * A_BUF;
                    const uint32_t bo = (uint32_t)c * 256;
#pragma unroll
                    for (int s = 0; s < 2; s++) {
                        const uint32_t ax = (uint32_t)(((c0log + 2 * s) ^ xorm) << 4);
                        uint32_t A0[4], A1[4], BH[4], BL[4];
                        ldsm4(A0, abuf + row0_off + ax);
                        ldsm4(A1, abuf + row0_off + 16384 + ax);
                        ldsm4(BH, bh_base + bo + s * 32);
                        ldsm4(BL, bl_base + bo + s * 32);
                        mma16816(accHH[0], A0, BH[0], BH[1]);   // ah*wh
                        mma16816(accHH[1], A0, BH[2], BH[3]);
                        mma16816(accLH[0], A1, BH[0], BH[1]);   // al*wh
                        mma16816(accLH[1], A1, BH[2], BH[3]);
                        mma16816(accHL[0], A0, BL[0], BL[1]);   // ah*wl
                        mma16816(accHL[1], A0, BL[2], BL[3]);
                    }
                }
            }
            __syncthreads();   // all warps done with A buffers -> stage overlay safe

            // write C fragments to stage[kq]: hi rows get HH+HL, lo rows get LH
            {
                const int r0 = 16 * mg + (lane >> 2);
                const int cc = 2 * (lane & 3);
                float* stg = stage + kq * (128 * 20);
#pragma unroll
                for (int nt = 0; nt < 2; nt++) {
                    const int col = 8 * nt + cc;
                    stg[r0 * 20 + col]            = accHH[nt][0] + accHL[nt][0];
                    stg[r0 * 20 + col + 1]        = accHH[nt][1] + accHL[nt][1];
                    stg[(r0 + 8) * 20 + col]      = accHH[nt][2] + accHL[nt][2];
                    stg[(r0 + 8) * 20 + col + 1]  = accHH[nt][3] + accHL[nt][3];
                    stg[(64 + r0) * 20 + col]     = accLH[nt][0];
                    stg[(64 + r0) * 20 + col + 1] = accLH[nt][1];
                    stg[(72 + r0) * 20 + col]     = accLH[nt][2];
                    stg[(72 + r0) * 20 + col + 1] = accLH[nt][3];
                }
            }
            __syncthreads();

            // combine k-quarters and hi/lo planes, bias, tanh, split-store h
            {
                float s0v = bv0, s1v = bv1;
#pragma unroll
                for (int q = 0; q < 4; q++) {
                    const float* st0 = stage + q * (128 * 20) + eb * 20 + en0;
                    const float* st1 = stage + q * (128 * 20) + (eb + 64) * 20 + en0;
                    s0v += st0[0] + st1[0];
                    s1v += st0[1] + st1[1];
                }
                float h0f = tanhf(s0v), h1f = tanhf(s1v);

                __nv_bfloat16 h0 = __float2bfloat16(h0f);
                __nv_bfloat16 h1 = __float2bfloat16(h1f);
                __nv_bfloat16 l0 = __float2bfloat16(h0f - __bfloat162float(h0));
                __nv_bfloat16 l1 = __float2bfloat16(h1f - __bfloat162float(h1));
                uint32_t hw = (uint32_t)*(uint16_t*)&h0 | ((uint32_t)*(uint16_t*)&h1 << 16);
                uint32_t lw = (uint32_t)*(uint16_t*)&l0 | ((uint32_t)*(uint16_t*)&l1 << 16);

                __nv_bfloat16* hp = layer ? g_h1s[p & 1] : g_h0s[p & 1];
                __stcg((uint32_t*)(hp + (size_t)eb * 1024 + jcta + en0), hw);
                __stcg((uint32_t*)(hp + (size_t)(eb + 64) * 1024 + jcta + en0), lw);

                float2 of = make_float2(h0f, h1f);
                if (layer) {
                    *(float2*)(out + ((size_t)eb * TT + t) * HH + jcta + en0) = of;
                    if (t == TT - 1)
                        *(float2*)(out + FSOFF + (size_t)eb * 2048 + 1024 + jcta + en0) = of;
                } else if (p == TT - 1) {
                    *(float2*)(out + FSOFF + (size_t)eb * 2048 + jcta + en0) = of;
                }
            }
        }

        // ---- grid barrier: per-phase counter ----
        __threadfence();
        __syncthreads();
        if (tid == 0) {
            atomicAdd(&g_cnt[p], 1);
            volatile int* cp = (volatile int*)&g_cnt[p];
            while (*cp < NCTA) { __nanosleep(32); }
        }
        __syncthreads();
    }
}

// ---------------------------------------------------------------------------
extern "C" void kernel_launch(void* const* d_in, const int* in_sizes, int n_in,
                              void* d_out, int out_size) {
    const float* x  = (const float*)d_in[0];
    const float* W0 = (const float*)d_in[1];
    const float* b0 = (const float*)d_in[2];
    const float* W1 = (const float*)d_in[3];
    const float* b1 = (const float*)d_in[4];
    float* out = (float*)d_out;

    cudaFuncSetAttribute(rnn_mma_kernel,
                         cudaFuncAttributeMaxDynamicSharedMemorySize, SMEM_BYTES);
    prep_all<<<512, 256>>>(x);
    rnn_mma_kernel<<<NCTA, THREADS, SMEM_BYTES>>>(W0, b0, W1, b1, out);
}

// round 12
// speedup vs baseline: 5.3059x; 1.0109x over previous
#include <cuda_runtime.h>
#include <cuda_bf16.h>
#include <cstdint>

#define TT 512
#define HH 1024
#define KDIM 2048
#define NCOL 16
#define THREADS 512
#define NCTA 128

// smem byte offsets
#define W_STRIDE 4112            // 2048 bf16 + 16B pad per n-row
#define WH_OFF 0                 // 16 * 4112 = 65792
#define WL_OFF 65792
#define A_OFF  131584            // 3 buffers x 32768 B (128 rows x 256 B, XOR-swizzled)
#define A_BUF  32768
#define STAGE_OFF A_OFF          // 8 planes x 128 x 20 floats = 81920 B (overlaid on A)
#define SMEM_BYTES 229888

__device__ __nv_bfloat16 g_xs[(size_t)128 * TT * 1024];   // x split planes: b<64 hi, b+64 lo
__device__ __nv_bfloat16 g_h0s[2][128 * 1024];
__device__ __nv_bfloat16 g_h1s[2][128 * 1024];
__device__ int g_cnt[TT + 2];

// ---------------------------------------------------------------------------
__device__ __forceinline__ uint32_t smem_u32(const void* p) {
    uint32_t a;
    asm("{ .reg .u64 t; cvta.to.shared.u64 t, %1; cvt.u32.u64 %0, t; }" : "=r"(a) : "l"(p));
    return a;
}
__device__ __forceinline__ void cp16(uint32_t d, const void* s) {
    asm volatile("cp.async.cg.shared.global [%0], [%1], 16;" :: "r"(d), "l"(s));
}
__device__ __forceinline__ void cp_commit() { asm volatile("cp.async.commit_group;"); }
template <int N>
__device__ __forceinline__ void cp_wait() { asm volatile("cp.async.wait_group %0;" :: "n"(N)); }

__device__ __forceinline__ void ldsm4(uint32_t* r, uint32_t addr) {
    asm volatile("ldmatrix.sync.aligned.m8n8.x4.shared.b16 {%0,%1,%2,%3}, [%4];"
        : "=r"(r[0]), "=r"(r[1]), "=r"(r[2]), "=r"(r[3]) : "r"(addr));
}
__device__ __forceinline__ void mma16816(float* c, const uint32_t* a, uint32_t b0, uint32_t b1) {
    asm volatile("mma.sync.aligned.m16n8k16.row.col.f32.bf16.bf16.f32 "
        "{%0,%1,%2,%3}, {%4,%5,%6,%7}, {%8,%9}, {%0,%1,%2,%3};"
        : "+f"(c[0]), "+f"(c[1]), "+f"(c[2]), "+f"(c[3])
        : "r"(a[0]), "r"(a[1]), "r"(a[2]), "r"(a[3]), "r"(b0), "r"(b1));
}

// ---------------------------------------------------------------------------
// Single prep kernel: zero states/counters + split x into bf16 hi/lo planes.
__global__ void prep_all(const float* __restrict__ x) {
    size_t i = (size_t)blockIdx.x * blockDim.x + threadIdx.x;
    size_t st = (size_t)gridDim.x * blockDim.x;
    __nv_bfloat16 z = __float2bfloat16(0.f);
    for (size_t k = i; k < 2 * 128 * 1024; k += st) { g_h0s[0][k] = z; g_h1s[0][k] = z; }
    for (size_t k = i; k < TT + 2; k += st) g_cnt[k] = 0;
    const size_t N = (size_t)64 * TT * 1024;
    for (size_t k = i; k < N; k += st) {
        float v = x[k];
        __nv_bfloat16 hi = __float2bfloat16(v);
        __nv_bfloat16 lo = __float2bfloat16(v - __bfloat162float(hi));
        size_t b = k >> 19, rest = k & ((1u << 19) - 1);   // T*H = 2^19
        g_xs[b * (size_t)(TT * 1024) + rest] = hi;
        g_xs[(b + 64) * (size_t)(TT * 1024) + rest] = lo;
    }
}

// ---------------------------------------------------------------------------
__global__ void __launch_bounds__(THREADS, 1)
rnn_mma_kernel(const float* __restrict__ W0, const float* __restrict__ b0,
               const float* __restrict__ W1, const float* __restrict__ b1,
               float* __restrict__ out) {
    extern __shared__ char smem[];
    const uint32_t sb = smem_u32(smem);
    float* stage = (float*)(smem + STAGE_OFF);   // 8 planes x 128 rows x 20 floats
    const int tid = threadIdx.x, w = tid >> 5, lane = tid & 31;
    const int mg = w & 1, kq = w >> 1;           // m-group 0..1, k-eighth 0..7
    const int cta = blockIdx.x, layer = cta >> 6, jcta = (cta & 63) * NCOL;
    const float* Wg   = layer ? W1 : W0;
    const float* bias = layer ? b1 : b0;

    // one-time: split W into SMEM, layout [n][k] bf16, row stride 4112B
    for (int i = tid; i < KDIM * NCOL; i += THREADS) {
        int k = i >> 4, n = i & 15;
        float v = Wg[(size_t)k * 1024 + jcta + n];
        __nv_bfloat16 hi = __float2bfloat16(v);
        __nv_bfloat16 lo = __float2bfloat16(v - __bfloat162float(hi));
        *(__nv_bfloat16*)(smem + WH_OFF + n * W_STRIDE + k * 2) = hi;
        *(__nv_bfloat16*)(smem + WL_OFF + n * W_STRIDE + k * 2) = lo;
    }

    // per-thread epilogue constants: thread -> (batch eb, col pair en0)
    const int eb = tid >> 3, en0 = (tid & 7) * 2;
    float bv0 = bias[jcta + en0], bv1 = bias[jcta + en0 + 1];

    // A fragment addressing (XOR-swizzled, 256B rows):
    //   phys_off(row, log16Bchunk) = row*256 + ((chunk ^ (row & 7)) << 4)
    const int arow = 32 * mg + (lane & 15);      // hi tile0 row for this lane
    const uint32_t row0_off = (uint32_t)arow << 8;
    const int c0log = 2 * kq + (lane >> 4);      // logical 16B-chunk (0..15)
    const int xorm = lane & 7;
    const uint32_t ax = (uint32_t)((c0log ^ xorm) << 4);
    const int bn = (lane & 7) + ((lane >> 4) << 3);
    const uint32_t bh_base = sb + WH_OFF + (uint32_t)bn * W_STRIDE
                           + (uint32_t)((lane >> 3) & 1) * 16 + (uint32_t)kq * 32;

    // cp.async mapping: thread -> (seg = logical chunk, rb = row base), rows rb+32j
    const int seg = tid & 15, rb = tid >> 4;     // rb 0..31
    const uint32_t dstbase = sb + A_OFF + ((uint32_t)rb << 8)
                           + (uint32_t)((seg ^ (rb & 7)) << 4);

    const size_t FSOFF = (size_t)64 * TT * HH;
    __syncthreads();

    for (int p = 0; p <= TT; p++) {
        const bool active = layer ? (p >= 1) : (p < TT);
        if (active) {
            const int t = layer ? (p - 1) : p;
            const __nv_bfloat16* s0;
            const __nv_bfloat16* s1;
            size_t rst1;
            if (layer) { s0 = g_h1s[(p + 1) & 1]; s1 = g_h0s[(p + 1) & 1]; rst1 = 1024; }
            else       { s0 = g_h0s[(p + 1) & 1]; s1 = g_xs + (size_t)t * 1024; rst1 = (size_t)TT * 1024; }

            float ah[2][2][4], al[2][2][4];
#pragma unroll
            for (int i = 0; i < 16; i++) { (&ah[0][0][0])[i] = 0.f; (&al[0][0][0])[i] = 0.f; }

            // prologue: stage chunks 0 and 1 (both from s0, k<1024)
#pragma unroll
            for (int cc = 0; cc < 2; cc++) {
                const uint32_t db = dstbase + (uint32_t)cc * A_BUF;
                const __nv_bfloat16* sp = s0 + (size_t)rb * 1024 + cc * 128 + seg * 8;
#pragma unroll
                for (int j = 0; j < 4; j++)
                    cp16(db + j * 8192, sp + (size_t)32 * j * 1024);
                cp_commit();
            }

            for (int c = 0; c < 16; c++) {
                if (c < 15) cp_wait<1>(); else cp_wait<0>();
                __syncthreads();   // chunk c visible + chunk c-1 consumers done

                if (c + 2 < 16) {
                    const int kb = (c + 2) * 128;
                    const __nv_bfloat16* srcb;
                    size_t rst;
                    if (kb < 1024) { srcb = s0 + kb; rst = 1024; }
                    else           { srcb = s1 + (kb - 1024); rst = rst1; }
                    const uint32_t db = dstbase + (uint32_t)((c + 2) % 3) * A_BUF;
                    const __nv_bfloat16* sp = srcb + (size_t)rb * rst + seg * 8;
#pragma unroll
                    for (int j = 0; j < 4; j++)
                        cp16(db + j * 8192, sp + (size_t)32 * j * rst);
                    cp_commit();
                }

                {
                    const uint32_t abase = sb + A_OFF + (uint32_t)(c % 3) * A_BUF
                                         + row0_off + ax;
                    uint32_t A0[4], A0b[4], A1[4], A1b[4], BH[4], BL[4];
                    ldsm4(A0,  abase);                 // hi tile 0
                    ldsm4(A0b, abase + 4096);          // hi tile 1 (+16 rows)
                    ldsm4(A1,  abase + 16384);         // lo tile 0 (+64 rows)
                    ldsm4(A1b, abase + 20480);         // lo tile 1 (+80 rows)
                    const uint32_t bo = bh_base + (uint32_t)c * 256;
                    ldsm4(BH, bo);
                    ldsm4(BL, bo + (WL_OFF - WH_OFF));
                    mma16816(ah[0][0], A0,  BH[0], BH[1]);   // ah*wh
                    mma16816(ah[0][1], A0,  BH[2], BH[3]);
                    mma16816(ah[1][0], A0b, BH[0], BH[1]);
                    mma16816(ah[1][1], A0b, BH[2], BH[3]);
                    mma16816(al[0][0], A1,  BH[0], BH[1]);   // al*wh
                    mma16816(al[0][1], A1,  BH[2], BH[3]);
                    mma16816(al[1][0], A1b, BH[0], BH[1]);
                    mma16816(al[1][1], A1b, BH[2], BH[3]);
                    mma16816(ah[0][0], A0,  BL[0], BL[1]);   // ah*wl (same acc)
                    mma16816(ah[0][1], A0,  BL[2], BL[3]);
                    mma16816(ah[1][0], A0b, BL[0], BL[1]);
                    mma16816(ah[1][1], A0b, BL[2], BL[3]);
                }
            }
            __syncthreads();   // all warps done with A buffers -> stage overlay safe

            // write C fragments to stage plane kq
            {
                const int r0 = 32 * mg + (lane >> 2);
                const int cc = 2 * (lane & 3);
                float* stg = stage + kq * (128 * 20);
#pragma unroll
                for (int tt2 = 0; tt2 < 2; tt2++) {
                    const int rbase = r0 + 16 * tt2;
#pragma unroll
                    for (int nt = 0; nt < 2; nt++) {
                        const int col = 8 * nt + cc;
                        stg[rbase * 20 + col]            = ah[tt2][nt][0];
                        stg[rbase * 20 + col + 1]        = ah[tt2][nt][1];
                        stg[(rbase + 8) * 20 + col]      = ah[tt2][nt][2];
                        stg[(rbase + 8) * 20 + col + 1]  = ah[tt2][nt][3];
                        stg[(64 + rbase) * 20 + col]     = al[tt2][nt][0];
                        stg[(64 + rbase) * 20 + col + 1] = al[tt2][nt][1];
                        stg[(72 + rbase) * 20 + col]     = al[tt2][nt][2];
                        stg[(72 + rbase) * 20 + col + 1] = al[tt2][nt][3];
                    }
                }
            }
            __syncthreads();

            // combine 8 k-planes and hi/lo rows, bias, tanh, split-store h
            {
                float s0v = bv0, s1v = bv1;
#pragma unroll
                for (int q = 0; q < 8; q++) {
                    const float* st0 = stage + q * (128 * 20) + eb * 20 + en0;
                    s0v += st0[0] + st0[64 * 20];
                    s1v += st0[1] + st0[64 * 20 + 1];
                }
                float h0f = tanhf(s0v), h1f = tanhf(s1v);

                __nv_bfloat16 h0 = __float2bfloat16(h0f);
                __nv_bfloat16 h1 = __float2bfloat16(h1f);
                __nv_bfloat16 l0 = __float2bfloat16(h0f - __bfloat162float(h0));
                __nv_bfloat16 l1 = __float2bfloat16(h1f - __bfloat162float(h1));
                uint32_t hw = (uint32_t)*(uint16_t*)&h0 | ((uint32_t)*(uint16_t*)&h1 << 16);
                uint32_t lw = (uint32_t)*(uint16_t*)&l0 | ((uint32_t)*(uint16_t*)&l1 << 16);

                __nv_bfloat16* hp = layer ? g_h1s[p & 1] : g_h0s[p & 1];
                __stcg((uint32_t*)(hp + (size_t)eb * 1024 + jcta + en0), hw);
                __stcg((uint32_t*)(hp + (size_t)(eb + 64) * 1024 + jcta + en0), lw);

                float2 of = make_float2(h0f, h1f);
                if (layer) {
                    *(float2*)(out + ((size_t)eb * TT + t) * HH + jcta + en0) = of;
                    if (t == TT - 1)
                        *(float2*)(out + FSOFF + (size_t)eb * 2048 + 1024 + jcta + en0) = of;
                } else if (p == TT - 1) {
                    *(float2*)(out + FSOFF + (size_t)eb * 2048 + jcta + en0) = of;
                }
            }
        }

        // ---- grid barrier: per-phase counter (verbatim R9, proven) ----
        __threadfence();
        __syncthreads();
        if (tid == 0) {
            atomicAdd(&g_cnt[p], 1);
            volatile int* cp = (volatile int*)&g_cnt[p];
            while (*cp < NCTA) { __nanosleep(32); }
        }
        __syncthreads();
    }
}

// ---------------------------------------------------------------------------
extern "C" void kernel_launch(void* const* d_in, const int* in_sizes, int n_in,
                              void* d_out, int out_size) {
    const float* x  = (const float*)d_in[0];
    const float* W0 = (const float*)d_in[1];
    const float* b0 = (const float*)d_in[2];
    const float* W1 = (const float*)d_in[3];
    const float* b1 = (const float*)d_in[4];
    float* out = (float*)d_out;

    cudaFuncSetAttribute(rnn_mma_kernel,
                         cudaFuncAttributeMaxDynamicSharedMemorySize, SMEM_BYTES);
    prep_all<<<512, 256>>>(x);
    rnn_mma_kernel<<<NCTA, THREADS, SMEM_BYTES>>>(W0, b0, W1, b1, out);
}